// round 4
// baseline (speedup 1.0000x reference)
#include <cuda_runtime.h>

typedef unsigned long long ull;

#define Hh 50      // hidden units
#define Gg 200     // 4*H gates
#define Tt 512     // timesteps
#define Bt 32      // batches per block
#define WS 52      // padded row stride, layer1 weights & c-state (floats)
#define CW 104     // concatenated layer2 row width [wih1(50)+pad2 | whh1(50)+pad2]
#define HS 108     // h01 row stride (27 float4, conflict-free: 12*l mod 32 distinct)
#define NT 512     // threads per block (16 warps)

// ---- pure register packing + packed fp32x2 FMA (CSE-safe: no memory operands) ----
__device__ __forceinline__ ull pack2(float x, float y) {
    ull r;
    asm("mov.b64 %0, {%1, %2};" : "=l"(r)
        : "r"(__float_as_uint(x)), "r"(__float_as_uint(y)));
    return r;
}
__device__ __forceinline__ ull ffma2(ull a, ull b, ull c) {
    ull d;
    asm("fma.rn.f32x2 %0, %1, %2, %3;" : "=l"(d) : "l"(a), "l"(b), "l"(c));
    return d;
}
__device__ __forceinline__ float f2sum(ull v) {
    unsigned lo, hi;
    asm("mov.b64 {%0, %1}, %2;" : "=r"(lo), "=r"(hi) : "l"(v));
    return __uint_as_float(lo) + __uint_as_float(hi);
}
__device__ __forceinline__ float sigm(float v) {
    float e = __expf(-v);
    return __fdividef(1.f, 1.f + e);
}
__device__ __forceinline__ float tanh_(float v) {
    float e = __expf(-2.f * v);
    return __fdividef(1.f - e, 1.f + e);
}

// shared layout (floats)
#define SM_W0    (Gg * WS)     // whh0 padded rows
#define SM_W1    (Gg * CW)     // [wih1|whh1] concatenated padded rows
#define SM_BIAS  (3 * Gg)      // b0, b1, wih0
#define SM_H01   (Bt * HS)     // [h0|h1] per batch
#define SM_C     (2 * Bt * WS) // c0, c1
#define SM_G     (Gg * Bt)
#define SM_X     (2 * Bt)
#define SM_FC    (Hh + 4)
#define SM_FLOATS (SM_W0 + SM_W1 + SM_BIAS + SM_H01 + SM_C + SM_G + SM_X + SM_FC)
#define SMEM_BYTES (SM_FLOATS * 4)

__global__ __launch_bounds__(NT, 1)
void lstm2_fused_kernel(
    const float* __restrict__ x,
    const float* __restrict__ wih0,   // (200,1)
    const float* __restrict__ whh0,   // (200,50)
    const float* __restrict__ bih0,
    const float* __restrict__ bhh0,
    const float* __restrict__ wih1,   // (200,50)
    const float* __restrict__ whh1,   // (200,50)
    const float* __restrict__ bih1,
    const float* __restrict__ bhh1,
    const float* __restrict__ fcw,    // (1,50)
    const float* __restrict__ fcb,    // (1)
    float* __restrict__ out)          // (B,1)
{
    extern __shared__ float sm[];
    float* s_whh0 = sm;                    // Gg*WS
    float* s_w1   = s_whh0 + Gg * WS;      // Gg*CW
    float* s_b0   = s_w1 + Gg * CW;        // Gg
    float* s_b1   = s_b0 + Gg;
    float* s_wih0 = s_b1 + Gg;
    float* s_h01  = s_wih0 + Gg;           // Bt*HS: [0:50)=h0, [52:102)=h1
    float* s_c0   = s_h01 + Bt * HS;       // Bt*WS
    float* s_c1   = s_c0 + Bt * WS;
    float* s_g    = s_c1 + Bt * WS;        // Gg*Bt
    float* s_x    = s_g + Gg * Bt;         // 2*Bt
    float* s_fc   = s_x + 2 * Bt;          // Hh+1

    const int tid  = threadIdx.x;
    const int lane = tid & 31;             // batch within tile
    const int wid  = tid >> 5;             // 0..15
    // rows per warp: warps 0-7 -> 13 rows, warps 8-15 -> 12 rows (8*13+8*12=200)
    const int rbeg = (wid < 8) ? 13 * wid : 104 + 12 * (wid - 8);
    const int rcnt = (wid < 8) ? 13 : 12;
    const int b0   = blockIdx.x * Bt;

    // ---- init: weights (padded, pads=0), biases, states ----
    for (int i = tid; i < Gg * WS; i += NT) {
        int j = i / WS, k = i - j * WS;
        s_whh0[i] = (k < Hh) ? whh0[j * Hh + k] : 0.f;
    }
    for (int i = tid; i < Gg * CW; i += NT) {
        int j = i / CW, k = i - j * CW;
        float v = 0.f;
        if (k < Hh)                    v = wih1[j * Hh + k];
        else if (k >= 52 && k < 52 + Hh) v = whh1[j * Hh + (k - 52)];
        s_w1[i] = v;
    }
    for (int i = tid; i < Gg; i += NT) {
        s_b0[i] = bih0[i] + bhh0[i];
        s_b1[i] = bih1[i] + bhh1[i];
        s_wih0[i] = wih0[i];
    }
    for (int i = tid; i < Bt * HS; i += NT) s_h01[i] = 0.f;
    for (int i = tid; i < 2 * Bt * WS; i += NT) s_c0[i] = 0.f;
    if (tid < Hh) s_fc[tid] = fcw[tid];
    if (tid == 0) s_fc[Hh] = fcb[0];
    if (tid < Bt) s_x[tid] = x[(ull)(b0 + tid) * Tt];
    __syncthreads();

    for (int t = 0; t < Tt; ++t) {
        float xnext = 0.f;
        if (tid < Bt && t + 1 < Tt) xnext = x[(ull)(b0 + tid) * Tt + (t + 1)];

        const float xv = s_x[(t & 1) * Bt + lane];

        // ---- layer 1 gates: g = b0 + x*wih0 + h0_prev . whh0^T ----
        {
            ull hr[26];
            const float4* hp = (const float4*)(s_h01 + lane * HS);  // h0 = first 50
            #pragma unroll
            for (int q = 0; q < 13; ++q) {
                float4 hv = hp[q];
                hr[2 * q]     = pack2(hv.x, hv.y);
                hr[2 * q + 1] = pack2(hv.z, hv.w);
            }
            // note: cols 50,51 of h01 are pads; whh0 pads are 0 so ok only if
            // h pads multiplied by zero weights -> true (w pads zero).
            for (int m = 0; m < rcnt; ++m) {
                const int j = rbeg + m;
                const float4* w = (const float4*)(s_whh0 + j * WS);
                ull a0 = 0ULL, a1 = 0ULL;
                #pragma unroll
                for (int q = 0; q < 13; ++q) {
                    float4 wv = w[q];
                    a0 = ffma2(pack2(wv.x, wv.y), hr[2 * q],     a0);
                    a1 = ffma2(pack2(wv.z, wv.w), hr[2 * q + 1], a1);
                }
                s_g[j * Bt + lane] = s_b0[j] + xv * s_wih0[j] + f2sum(a0) + f2sum(a1);
            }
        }
        __syncthreads();

        // ---- layer 1 cell update: writes h0 into h01[b][0:50] ----
        for (int idx = tid; idx < Hh * Bt; idx += NT) {
            int u = idx >> 5, b = idx & 31;
            float gi = sigm (s_g[(u         ) * Bt + b]);
            float gf = sigm (s_g[(u +     Hh) * Bt + b]);
            float gg = tanh_(s_g[(u + 2 * Hh) * Bt + b]);
            float go = sigm (s_g[(u + 3 * Hh) * Bt + b]);
            float c = gf * s_c0[b * WS + u] + gi * gg;
            s_c0[b * WS + u] = c;
            s_h01[b * HS + u] = go * tanh_(c);
        }
        __syncthreads();

        // ---- layer 2 gates: g = b1 + [h0_cur|h1_prev] . [wih1|whh1]^T ----
        {
            ull hr[26];
            const float4* hp = (const float4*)(s_h01 + lane * HS);  // 104 floats
            #pragma unroll
            for (int q = 0; q < 26; ++q) {
                float4 hv = hp[q];
                hr[q] = pack2(hv.x, hv.y);
                // NOTE: store both halves: use two entries
                // handled below by unrolled pair loads
                (void)hv;
            }
            // redo properly: 26 float4 -> 52 halves is too many regs; instead
            // accumulate inline without persistent h array for second half.
            // Load as pairs directly in the row loop is expensive; so split:
            // we keep 26 ull covering 52 floats at a time (two passes).
            // ---- pass structure below ----
        }
        {
            // two-pass: pass 0 covers floats [0:52) (h0 + pads),
            //           pass 1 covers floats [52:104) (h1 + pads).
            float accv[13];   // partial gate values for this warp's rows
            #pragma unroll
            for (int m = 0; m < 13; ++m) accv[m] = 0.f;

            #pragma unroll
            for (int pass = 0; pass < 2; ++pass) {
                ull hr[26];
                const float4* hp = (const float4*)(s_h01 + lane * HS + pass * 52);
                #pragma unroll
                for (int q = 0; q < 13; ++q) {
                    float4 hv = hp[q];
                    hr[2 * q]     = pack2(hv.x, hv.y);
                    hr[2 * q + 1] = pack2(hv.z, hv.w);
                }
                for (int m = 0; m < rcnt; ++m) {
                    const int j = rbeg + m;
                    const float4* w = (const float4*)(s_w1 + j * CW + pass * 52);
                    ull a0 = 0ULL, a1 = 0ULL;
                    #pragma unroll
                    for (int q = 0; q < 13; ++q) {
                        float4 wv = w[q];
                        a0 = ffma2(pack2(wv.x, wv.y), hr[2 * q],     a0);
                        a1 = ffma2(pack2(wv.z, wv.w), hr[2 * q + 1], a1);
                    }
                    accv[m] += f2sum(a0) + f2sum(a1);
                }
            }
            for (int m = 0; m < rcnt; ++m) {
                const int j = rbeg + m;
                s_g[j * Bt + lane] = s_b1[j] + accv[m];
            }
        }
        __syncthreads();

        // ---- layer 2 cell update: writes h1 into h01[b][52:102] ----
        for (int idx = tid; idx < Hh * Bt; idx += NT) {
            int u = idx >> 5, b = idx & 31;
            float gi = sigm (s_g[(u         ) * Bt + b]);
            float gf = sigm (s_g[(u +     Hh) * Bt + b]);
            float gg = tanh_(s_g[(u + 2 * Hh) * Bt + b]);
            float go = sigm (s_g[(u + 3 * Hh) * Bt + b]);
            float c = gf * s_c1[b * WS + u] + gi * gg;
            s_c1[b * WS + u] = c;
            s_h01[b * HS + 52 + u] = go * tanh_(c);
        }
        if (tid < Bt) s_x[((t + 1) & 1) * Bt + tid] = xnext;
        __syncthreads();
    }

    // ---- final FC on last h1 ----
    if (tid < Bt) {
        float acc = s_fc[Hh];
        const float* h = s_h01 + tid * HS + 52;
        #pragma unroll
        for (int k = 0; k < Hh; ++k) acc += h[k] * s_fc[k];
        out[b0 + tid] = acc;
    }
}

extern "C" void kernel_launch(void* const* d_in, const int* in_sizes, int n_in,
                              void* d_out, int out_size)
{
    const float* x    = (const float*)d_in[0];
    const float* wih0 = (const float*)d_in[1];
    const float* whh0 = (const float*)d_in[2];
    const float* bih0 = (const float*)d_in[3];
    const float* bhh0 = (const float*)d_in[4];
    const float* wih1 = (const float*)d_in[5];
    const float* whh1 = (const float*)d_in[6];
    const float* bih1 = (const float*)d_in[7];
    const float* bhh1 = (const float*)d_in[8];
    const float* fcw  = (const float*)d_in[9];
    const float* fcb  = (const float*)d_in[10];
    float* out = (float*)d_out;

    const int B = in_sizes[0] / Tt;   // 4096
    const int grid = B / Bt;          // 128 blocks

    cudaFuncSetAttribute(lstm2_fused_kernel,
                         cudaFuncAttributeMaxDynamicSharedMemorySize, SMEM_BYTES);

    lstm2_fused_kernel<<<grid, NT, SMEM_BYTES>>>(
        x, wih0, whh0, bih0, bhh0, wih1, whh1, bih1, bhh1, fcw, fcb, out);
}

// round 9
// speedup vs baseline: 2.6923x; 2.6923x over previous
#include <cuda_runtime.h>
#include <cuda_fp16.h>

typedef unsigned long long ull;

#define NT 416        // 13 warps
#define Tt 512
#define Hh 50

// shared memory byte offsets (16B aligned)
#define OFF_A   0u        // prepacked A fragments: 139 slots x (hi512|lo512) = 142336B
#define OFF_B   142336u   // h buffer f16: hi 112 rows x 80B ; lo at +8960
#define B_LO    8960u
#define OFF_G   160256u   // gates f32: 400 rows x 160B = 64000B
#define OFF_BI0 224256u   // b0 200 f32
#define OFF_BI1 225056u   // b1
#define OFF_WI0 225856u   // wih0
#define OFF_FC  226656u   // fc[50] + fcb
#define OFF_X   226864u   // x buffer 32 f32
#define SMEM_BYTES 227008u

#define LDMX4T(r0,r1,r2,r3,a) \
  asm volatile("ldmatrix.sync.aligned.m8n8.x4.trans.shared.b16 {%0,%1,%2,%3}, [%4];" \
    : "=r"(r0),"=r"(r1),"=r"(r2),"=r"(r3) : "r"(a))

__device__ __forceinline__ void mma16816(float* d, const uint4& a,
                                         unsigned b0, unsigned b1) {
    asm volatile("mma.sync.aligned.m16n8k16.row.col.f32.f16.f16.f32 "
        "{%0,%1,%2,%3}, {%4,%5,%6,%7}, {%8,%9}, {%0,%1,%2,%3};"
        : "+f"(d[0]), "+f"(d[1]), "+f"(d[2]), "+f"(d[3])
        : "r"(a.x), "r"(a.y), "r"(a.z), "r"(a.w), "r"(b0), "r"(b1));
}
__device__ __forceinline__ float rcpa(float v) {
    float r; asm("rcp.approx.f32 %0, %1;" : "=f"(r) : "f"(v)); return r;
}
__device__ __forceinline__ float ex2a(float v) {   // 2^v
    float r; asm("ex2.approx.f32 %0, %1;" : "=f"(r) : "f"(v)); return r;
}
#define L2E  1.4426950408889634f
#define L2E2 2.8853901617779268f

// A_big[400][112]: rows 0-199 = [whh0(k<50) | 0]; rows 200-399 = [wih1 | whh1 | 0]
__device__ __forceinline__ float valA(int M, int k,
    const float* __restrict__ whh0, const float* __restrict__ wih1,
    const float* __restrict__ whh1) {
    if (k >= 100) return 0.f;
    if (M < 200) return (k < Hh) ? whh0[M * Hh + k] : 0.f;
    int r = M - 200;
    return (k < Hh) ? wih1[r * Hh + k] : whh1[r * Hh + (k - Hh)];
}

__global__ __launch_bounds__(NT, 1)
void lstm2_hmma_kernel(
    const float* __restrict__ x,
    const float* __restrict__ wih0, const float* __restrict__ whh0,
    const float* __restrict__ bih0, const float* __restrict__ bhh0,
    const float* __restrict__ wih1, const float* __restrict__ whh1,
    const float* __restrict__ bih1, const float* __restrict__ bhh1,
    const float* __restrict__ fcw,  const float* __restrict__ fcb,
    float* __restrict__ out)
{
    extern __shared__ char smp[];
    const unsigned sb = (unsigned)__cvta_generic_to_shared(smp);

    const int tid  = threadIdx.x;
    const int lane = tid & 31;
    const int wid  = tid >> 5;              // 0..12
    const int b0i  = blockIdx.x * 32;

    // ---------------- init ----------------
    // zero h-buffer + gates (contiguous region)
    for (unsigned i = tid * 4u; i < 81920u; i += NT * 4u)
        *(float*)(smp + OFF_B + i) = 0.f;

    // prepack A fragments: 139 (m,s) slots x 2 halves x 32 lanes x 4 regs
    for (int e = tid; e < 139 * 256; e += NT) {
        int r    = e & 3;
        int L    = (e >> 2) & 31;
        int half = (e >> 7) & 1;
        int fi   = e >> 8;
        int m, s;
        if (fi < 48) { m = fi >> 2; s = fi & 3; }
        else { int q = fi - 48; m = 12 + q / 7; s = q - 7 * (m - 12); }
        int row = 16 * m + (L >> 2) + (r & 1) * 8;
        int k   = 16 * s + (L & 3) * 2 + (r >> 1) * 8;
        float v0 = valA(row, k,     whh0, wih1, whh1);
        float v1 = valA(row, k + 1, whh0, wih1, whh1);
        __half h0 = __float2half_rn(v0), h1 = __float2half_rn(v1);
        __half2 o;
        if (half == 0) o = __halves2half2(h0, h1);
        else o = __halves2half2(__float2half_rn(v0 - __half2float(h0)),
                                __float2half_rn(v1 - __half2float(h1)));
        *(__half2*)(smp + OFF_A + (unsigned)fi * 1024u + (unsigned)half * 512u
                    + (unsigned)L * 16u + (unsigned)r * 4u) = o;
    }
    for (int i = tid; i < 200; i += NT) {
        *(float*)(smp + OFF_BI0 + i * 4) = bih0[i] + bhh0[i];
        *(float*)(smp + OFF_BI1 + i * 4) = bih1[i] + bhh1[i];
        *(float*)(smp + OFF_WI0 + i * 4) = wih0[i];
    }
    if (tid < Hh) *(float*)(smp + OFF_FC + tid * 4) = fcw[tid];
    if (tid == Hh) *(float*)(smp + OFF_FC + 200) = fcb[0];
    if (tid < 32) *(float*)(smp + OFF_X + tid * 4) = x[(ull)(b0i + tid) * Tt];
    __syncthreads();

    // ---------------- per-warp GEMM constants ----------------
    const int  m0 = 2 * wid, m1 = m0 + 1;
    const bool two = (wid < 12);
    const int  ns = (m0 < 12) ? 4 : 7;
    const unsigned fi0 = (m0 < 12) ? 4u * m0 : 48u + 7u * (m0 - 12);
    const unsigned fi1 = two ? ((m1 < 12) ? 4u * m1 : 48u + 7u * (m1 - 12)) : fi0;
    const unsigned offA0 = OFF_A + fi0 * 1024u + (unsigned)lane * 16u;
    const unsigned offA1 = OFF_A + fi1 * 1024u + (unsigned)lane * 16u;
    const unsigned ko  = (lane & 7) + 8 * ((lane >> 3) & 1);
    const unsigned nto = lane >> 4;
    const unsigned bAddr = sb + OFF_B + ko * 80u + nto * 16u;
    const unsigned gid = lane >> 2, tig = lane & 3;
    const unsigned offG0 = OFF_G + (16u * m0 + gid) * 160u + tig * 8u;
    const unsigned offG1 = OFF_G + (16u * m1 + gid) * 160u + tig * 8u;

    // persistent cell state: item i -> (layer, u-pair, b); up to 4 items x 2 units
    float cst[4][2];
    #pragma unroll
    for (int i = 0; i < 4; ++i) { cst[i][0] = 0.f; cst[i][1] = 0.f; }

    // fused cell section: layer-1 part = cell1(t+1) (uses x(t+1) in OFF_X),
    // layer-2 part = cell2(t). Writes h into f16 hi/lo B buffer.
    auto cells = [&](int t, bool dol1, bool dol2) {
        #pragma unroll
        for (int i = 0; i < 4; ++i) {
            int idx = tid + NT * i;
            if (idx >= 1600) break;
            int layer = (idx >= 800) ? 1 : 0;
            int p = idx - 800 * layer;
            int u = 2 * (p >> 5), b = p & 31;
            if (layer ? !dol2 : !dol1) continue;
            int gbase = layer * 200;
            float xb = layer ? 0.f : *(const float*)(smp + OFF_X + b * 4);
            #pragma unroll
            for (int j = 0; j < 2; ++j) {
                int uu = u + j;
                int r0 = gbase + uu;
                float gi = *(const float*)(smp + OFF_G + (r0        ) * 160u + b * 4u);
                float gf = *(const float*)(smp + OFF_G + (r0 +  Hh  ) * 160u + b * 4u);
                float gg = *(const float*)(smp + OFF_G + (r0 + 2*Hh ) * 160u + b * 4u);
                float go = *(const float*)(smp + OFF_G + (r0 + 3*Hh ) * 160u + b * 4u);
                if (layer == 0) {
                    gi += *(const float*)(smp + OFF_BI0 + (uu        ) * 4u)
                        + *(const float*)(smp + OFF_WI0 + (uu        ) * 4u) * xb;
                    gf += *(const float*)(smp + OFF_BI0 + (uu +  Hh  ) * 4u)
                        + *(const float*)(smp + OFF_WI0 + (uu +  Hh  ) * 4u) * xb;
                    gg += *(const float*)(smp + OFF_BI0 + (uu + 2*Hh ) * 4u)
                        + *(const float*)(smp + OFF_WI0 + (uu + 2*Hh ) * 4u) * xb;
                    go += *(const float*)(smp + OFF_BI0 + (uu + 3*Hh ) * 4u)
                        + *(const float*)(smp + OFF_WI0 + (uu + 3*Hh ) * 4u) * xb;
                } else {
                    gi += *(const float*)(smp + OFF_BI1 + (uu        ) * 4u);
                    gf += *(const float*)(smp + OFF_BI1 + (uu +  Hh  ) * 4u);
                    gg += *(const float*)(smp + OFF_BI1 + (uu + 2*Hh ) * 4u);
                    go += *(const float*)(smp + OFF_BI1 + (uu + 3*Hh ) * 4u);
                }
                float ei = ex2a(-L2E  * gi);
                float ef = ex2a(-L2E  * gf);
                float eg = ex2a(-L2E2 * gg);
                float eo = ex2a(-L2E  * go);
                float rig = rcpa((1.f + ei) * (1.f + eg));   // i * tanh(gg) = (1-eg)*rig
                float f   = rcpa(1.f + ef);
                float c   = f * cst[i][j] + (1.f - eg) * rig;
                cst[i][j] = c;
                float ec  = ex2a(-L2E2 * c);
                float h   = (1.f - ec) * rcpa((1.f + eo) * (1.f + ec)); // o*tanh(c)
                int kk = layer * Hh + uu;
                __half hh = __float2half_rn(h);
                *(__half*)(smp + OFF_B + kk * 80u + b * 2u) = hh;
                *(__half*)(smp + OFF_B + B_LO + kk * 80u + b * 2u) =
                    __float2half_rn(h - __half2float(hh));
                if (layer == 1 && t == Tt - 1)   // stash f32 h1 for the FC
                    *(float*)(smp + OFF_G + (200 + uu) * 160u + b * 4u) = h;
            }
        }
    };

    // pre-loop: cell1(0) from zero gates (G zeroed) + x(0)
    cells(-1, true, false);
    __syncthreads();

    // ---------------- timestep loop ----------------
    for (int t = 0; t < Tt; ++t) {
        // prefetch x(t+1) for the cell section
        if (tid < 32 && t + 1 < Tt)
            *(float*)(smp + OFF_X + tid * 4) = x[(ull)(b0i + tid) * Tt + t + 1];

        // ---- GEMM: D[400x32] = A_big x [h0(t); h1(t-1)] (3-term f16 split) ----
        float D0[4][4], D1[4][4];
        #pragma unroll
        for (int n = 0; n < 4; ++n)
            #pragma unroll
            for (int q = 0; q < 4; ++q) { D0[n][q] = 0.f; D1[n][q] = 0.f; }

        for (int s = 0; s < ns; ++s) {
            unsigned ba = bAddr + (unsigned)s * 1280u;
            unsigned bh[8], bl[8];
            LDMX4T(bh[0], bh[1], bh[2], bh[3], ba);
            LDMX4T(bh[4], bh[5], bh[6], bh[7], ba + 32u);
            LDMX4T(bl[0], bl[1], bl[2], bl[3], ba + B_LO);
            LDMX4T(bl[4], bl[5], bl[6], bl[7], ba + B_LO + 32u);

            uint4 ah = *(const uint4*)(smp + offA0 + (unsigned)s * 1024u);
            uint4 al = *(const uint4*)(smp + offA0 + (unsigned)s * 1024u + 512u);
            #pragma unroll
            for (int n = 0; n < 4; ++n) mma16816(D0[n], ah, bh[2*n], bh[2*n+1]);
            #pragma unroll
            for (int n = 0; n < 4; ++n) mma16816(D0[n], al, bh[2*n], bh[2*n+1]);
            #pragma unroll
            for (int n = 0; n < 4; ++n) mma16816(D0[n], ah, bl[2*n], bl[2*n+1]);

            if (two) {
                uint4 ah1 = *(const uint4*)(smp + offA1 + (unsigned)s * 1024u);
                uint4 al1 = *(const uint4*)(smp + offA1 + (unsigned)s * 1024u + 512u);
                #pragma unroll
                for (int n = 0; n < 4; ++n) mma16816(D1[n], ah1, bh[2*n], bh[2*n+1]);
                #pragma unroll
                for (int n = 0; n < 4; ++n) mma16816(D1[n], al1, bh[2*n], bh[2*n+1]);
                #pragma unroll
                for (int n = 0; n < 4; ++n) mma16816(D1[n], ah1, bl[2*n], bl[2*n+1]);
            }
        }
        // store gate pre-activations
        #pragma unroll
        for (int n = 0; n < 4; ++n) {
            *(float2*)(smp + offG0 + n * 32u)            = make_float2(D0[n][0], D0[n][1]);
            *(float2*)(smp + offG0 + n * 32u + 8u*160u)  = make_float2(D0[n][2], D0[n][3]);
            if (two) {
                *(float2*)(smp + offG1 + n * 32u)           = make_float2(D1[n][0], D1[n][1]);
                *(float2*)(smp + offG1 + n * 32u + 8u*160u) = make_float2(D1[n][2], D1[n][3]);
            }
        }
        __syncthreads();

        // ---- cells: cell2(t) + cell1(t+1) ----
        cells(t, t + 1 < Tt, true);
        __syncthreads();
    }

    // ---------------- final FC on h1(511) (f32 stash in G rows 200-249) ----------------
    if (tid < 32) {
        float acc = *(const float*)(smp + OFF_FC + 200);
        #pragma unroll
        for (int u = 0; u < Hh; ++u)
            acc += *(const float*)(smp + OFF_FC + u * 4)
                 * *(const float*)(smp + OFF_G + (200 + u) * 160u + tid * 4u);
        out[b0i + tid] = acc;
    }
}

extern "C" void kernel_launch(void* const* d_in, const int* in_sizes, int n_in,
                              void* d_out, int out_size)
{
    const float* x    = (const float*)d_in[0];
    const float* wih0 = (const float*)d_in[1];
    const float* whh0 = (const float*)d_in[2];
    const float* bih0 = (const float*)d_in[3];
    const float* bhh0 = (const float*)d_in[4];
    const float* wih1 = (const float*)d_in[5];
    const float* whh1 = (const float*)d_in[6];
    const float* bih1 = (const float*)d_in[7];
    const float* bhh1 = (const float*)d_in[8];
    const float* fcw  = (const float*)d_in[9];
    const float* fcb  = (const float*)d_in[10];
    float* out = (float*)d_out;

    const int B = in_sizes[0] / Tt;   // 4096
    const int grid = B / 32;          // 128

    cudaFuncSetAttribute(lstm2_hmma_kernel,
                         cudaFuncAttributeMaxDynamicSharedMemorySize, SMEM_BYTES);

    lstm2_hmma_kernel<<<grid, NT, SMEM_BYTES>>>(
        x, wih0, whh0, bih0, bhh0, wih1, whh1, bih1, bhh1, fcw, fcb, out);
}

// round 11
// speedup vs baseline: 2.6934x; 1.0004x over previous
#include <cuda_runtime.h>
#include <cuda_fp16.h>

typedef unsigned long long ull;

#define NT 416        // 13 warps
#define Tt 512
#define Hh 50

// shared memory byte offsets (16B aligned)
#define OFF_A   0u        // prepacked A fragments: 139 slots x (hi512|lo512) = 142336B
#define OFF_B   142336u   // h buffer f16: hi 112 rows x 80B ; lo at +8960
#define B_LO    8960u
#define OFF_G   160256u   // gates f32: 400 rows x 160B = 64000B
#define OFF_BI0 224256u   // b0 200 f32
#define OFF_BI1 225056u   // b1
#define OFF_WI0 225856u   // wih0
#define OFF_FC  226656u   // fc[50] + fcb
#define OFF_X   226864u   // x buffer 32 f32
#define SMEM_BYTES 227008u

#define LDMX4T(r0,r1,r2,r3,a) \
  asm volatile("ldmatrix.sync.aligned.m8n8.x4.trans.shared.b16 {%0,%1,%2,%3}, [%4];" \
    : "=r"(r0),"=r"(r1),"=r"(r2),"=r"(r3) : "r"(a))

__device__ __forceinline__ void mma16816(float* d, const uint4& a,
                                         unsigned b0, unsigned b1) {
    asm volatile("mma.sync.aligned.m16n8k16.row.col.f32.f16.f16.f32 "
        "{%0,%1,%2,%3}, {%4,%5,%6,%7}, {%8,%9}, {%0,%1,%2,%3};"
        : "+f"(d[0]), "+f"(d[1]), "+f"(d[2]), "+f"(d[3])
        : "r"(a.x), "r"(a.y), "r"(a.z), "r"(a.w), "r"(b0), "r"(b1));
}
__device__ __forceinline__ float rcpa(float v) {
    float r; asm("rcp.approx.f32 %0, %1;" : "=f"(r) : "f"(v)); return r;
}
__device__ __forceinline__ float ex2a(float v) {   // 2^v
    float r; asm("ex2.approx.f32 %0, %1;" : "=f"(r) : "f"(v)); return r;
}
#define L2E  1.4426950408889634f
#define L2E2 2.8853901617779268f

// A_big[400][112]: rows 0-199 = [whh0(k<50) | 0]; rows 200-399 = [wih1 | whh1 | 0]
__device__ __forceinline__ float valA(int M, int k,
    const float* __restrict__ whh0, const float* __restrict__ wih1,
    const float* __restrict__ whh1) {
    if (k >= 100) return 0.f;
    if (M < 200) return (k < Hh) ? whh0[M * Hh + k] : 0.f;
    int r = M - 200;
    return (k < Hh) ? wih1[r * Hh + k] : whh1[r * Hh + (k - Hh)];
}

__global__ __launch_bounds__(NT, 1)
void lstm2_hmma_kernel(
    const float* __restrict__ x,
    const float* __restrict__ wih0, const float* __restrict__ whh0,
    const float* __restrict__ bih0, const float* __restrict__ bhh0,
    const float* __restrict__ wih1, const float* __restrict__ whh1,
    const float* __restrict__ bih1, const float* __restrict__ bhh1,
    const float* __restrict__ fcw,  const float* __restrict__ fcb,
    float* __restrict__ out)
{
    extern __shared__ char smp[];
    const unsigned sb = (unsigned)__cvta_generic_to_shared(smp);

    const int tid  = threadIdx.x;
    const int lane = tid & 31;
    const int wid  = tid >> 5;              // 0..12
    const int b0i  = blockIdx.x * 32;

    // ---------------- init ----------------
    // zero h-buffer + gates (contiguous region)
    for (unsigned i = tid * 4u; i < 81920u; i += NT * 4u)
        *(float*)(smp + OFF_B + i) = 0.f;

    // prepack A fragments: 139 (m,s) slots x 2 halves x 32 lanes x 4 regs
    for (int e = tid; e < 139 * 256; e += NT) {
        int r    = e & 3;
        int L    = (e >> 2) & 31;
        int half = (e >> 7) & 1;
        int fi   = e >> 8;
        int m, s;
        if (fi < 48) { m = fi >> 2; s = fi & 3; }
        else { int q = fi - 48; m = 12 + q / 7; s = q - 7 * (m - 12); }
        int row = 16 * m + (L >> 2) + (r & 1) * 8;
        int k   = 16 * s + (L & 3) * 2 + (r >> 1) * 8;
        float v0 = valA(row, k,     whh0, wih1, whh1);
        float v1 = valA(row, k + 1, whh0, wih1, whh1);
        __half h0 = __float2half_rn(v0), h1 = __float2half_rn(v1);
        __half2 o;
        if (half == 0) o = __halves2half2(h0, h1);
        else o = __halves2half2(__float2half_rn(v0 - __half2float(h0)),
                                __float2half_rn(v1 - __half2float(h1)));
        *(__half2*)(smp + OFF_A + (unsigned)fi * 1024u + (unsigned)half * 512u
                    + (unsigned)L * 16u + (unsigned)r * 4u) = o;
    }
    for (int i = tid; i < 200; i += NT) {
        *(float*)(smp + OFF_BI0 + i * 4) = bih0[i] + bhh0[i];
        *(float*)(smp + OFF_BI1 + i * 4) = bih1[i] + bhh1[i];
        *(float*)(smp + OFF_WI0 + i * 4) = wih0[i];
    }
    if (tid < Hh) *(float*)(smp + OFF_FC + tid * 4) = fcw[tid];
    if (tid == Hh) *(float*)(smp + OFF_FC + 200) = fcb[0];
    if (tid < 32) *(float*)(smp + OFF_X + tid * 4) = x[(ull)(b0i + tid) * Tt];
    __syncthreads();

    // ---------------- per-warp GEMM constants ----------------
    const int  m0 = 2 * wid, m1 = m0 + 1;
    const bool two = (wid < 12);
    const int  ns = (m0 < 12) ? 4 : 7;
    const unsigned fi0 = (m0 < 12) ? 4u * m0 : 48u + 7u * (m0 - 12);
    const unsigned fi1 = two ? ((m1 < 12) ? 4u * m1 : 48u + 7u * (m1 - 12)) : fi0;
    const unsigned offA0 = OFF_A + fi0 * 1024u + (unsigned)lane * 16u;
    const unsigned offA1 = OFF_A + fi1 * 1024u + (unsigned)lane * 16u;
    const unsigned ko  = (lane & 7) + 8 * ((lane >> 3) & 1);
    const unsigned nto = lane >> 4;
    const unsigned bAddr = sb + OFF_B + ko * 80u + nto * 16u;
    const unsigned gid = lane >> 2, tig = lane & 3;
    const unsigned offG0 = OFF_G + (16u * m0 + gid) * 160u + tig * 8u;
    const unsigned offG1 = OFF_G + (16u * m1 + gid) * 160u + tig * 8u;

    // persistent cell state: item i -> (layer, u-pair, b); up to 4 items x 2 units
    float cst[4][2];
    #pragma unroll
    for (int i = 0; i < 4; ++i) { cst[i][0] = 0.f; cst[i][1] = 0.f; }

    // fused cell section: layer-1 part = cell1(t+1) (uses x(t+1) in OFF_X),
    // layer-2 part = cell2(t). Writes h into f16 hi/lo B buffer.
    auto cells = [&](int t, bool dol1, bool dol2) {
        #pragma unroll
        for (int i = 0; i < 4; ++i) {
            int idx = tid + NT * i;
            if (idx >= 1600) break;
            int layer = (idx >= 800) ? 1 : 0;
            int p = idx - 800 * layer;
            int u = 2 * (p >> 5), b = p & 31;
            if (layer ? !dol2 : !dol1) continue;
            int gbase = layer * 200;
            float xb = layer ? 0.f : *(const float*)(smp + OFF_X + b * 4);
            #pragma unroll
            for (int j = 0; j < 2; ++j) {
                int uu = u + j;
                int r0 = gbase + uu;
                float gi = *(const float*)(smp + OFF_G + (r0        ) * 160u + b * 4u);
                float gf = *(const float*)(smp + OFF_G + (r0 +  Hh  ) * 160u + b * 4u);
                float gg = *(const float*)(smp + OFF_G + (r0 + 2*Hh ) * 160u + b * 4u);
                float go = *(const float*)(smp + OFF_G + (r0 + 3*Hh ) * 160u + b * 4u);
                if (layer == 0) {
                    gi += *(const float*)(smp + OFF_BI0 + (uu        ) * 4u)
                        + *(const float*)(smp + OFF_WI0 + (uu        ) * 4u) * xb;
                    gf += *(const float*)(smp + OFF_BI0 + (uu +  Hh  ) * 4u)
                        + *(const float*)(smp + OFF_WI0 + (uu +  Hh  ) * 4u) * xb;
                    gg += *(const float*)(smp + OFF_BI0 + (uu + 2*Hh ) * 4u)
                        + *(const float*)(smp + OFF_WI0 + (uu + 2*Hh ) * 4u) * xb;
                    go += *(const float*)(smp + OFF_BI0 + (uu + 3*Hh ) * 4u)
                        + *(const float*)(smp + OFF_WI0 + (uu + 3*Hh ) * 4u) * xb;
                } else {
                    gi += *(const float*)(smp + OFF_BI1 + (uu        ) * 4u);
                    gf += *(const float*)(smp + OFF_BI1 + (uu +  Hh  ) * 4u);
                    gg += *(const float*)(smp + OFF_BI1 + (uu + 2*Hh ) * 4u);
                    go += *(const float*)(smp + OFF_BI1 + (uu + 3*Hh ) * 4u);
                }
                float ei = ex2a(-L2E  * gi);
                float ef = ex2a(-L2E  * gf);
                float eg = ex2a(-L2E2 * gg);
                float eo = ex2a(-L2E  * go);
                float rig = rcpa((1.f + ei) * (1.f + eg));   // i * tanh(gg) = (1-eg)*rig
                float f   = rcpa(1.f + ef);
                float c   = f * cst[i][j] + (1.f - eg) * rig;
                cst[i][j] = c;
                float ec  = ex2a(-L2E2 * c);
                float h   = (1.f - ec) * rcpa((1.f + eo) * (1.f + ec)); // o*tanh(c)
                int kk = layer * Hh + uu;
                __half hh = __float2half_rn(h);
                *(__half*)(smp + OFF_B + kk * 80u + b * 2u) = hh;
                *(__half*)(smp + OFF_B + B_LO + kk * 80u + b * 2u) =
                    __float2half_rn(h - __half2float(hh));
                if (layer == 1 && t == Tt - 1)   // stash f32 h1 for the FC
                    *(float*)(smp + OFF_G + (200 + uu) * 160u + b * 4u) = h;
            }
        }
    };

    // pre-loop: cell1(0) from zero gates (G zeroed) + x(0)
    cells(-1, true, false);
    __syncthreads();

    // ---------------- timestep loop ----------------
    for (int t = 0; t < Tt; ++t) {
        // prefetch x(t+1) for the cell section
        if (tid < 32 && t + 1 < Tt)
            *(float*)(smp + OFF_X + tid * 4) = x[(ull)(b0i + tid) * Tt + t + 1];

        // ---- GEMM: D[400x32] = A_big x [h0(t); h1(t-1)] (3-term f16 split) ----
        float D0[4][4], D1[4][4];
        #pragma unroll
        for (int n = 0; n < 4; ++n)
            #pragma unroll
            for (int q = 0; q < 4; ++q) { D0[n][q] = 0.f; D1[n][q] = 0.f; }

        for (int s = 0; s < ns; ++s) {
            unsigned ba = bAddr + (unsigned)s * 1280u;
            unsigned bh[8], bl[8];
            LDMX4T(bh[0], bh[1], bh[2], bh[3], ba);
            LDMX4T(bh[4], bh[5], bh[6], bh[7], ba + 32u);
            LDMX4T(bl[0], bl[1], bl[2], bl[3], ba + B_LO);
            LDMX4T(bl[4], bl[5], bl[6], bl[7], ba + B_LO + 32u);

            uint4 ah = *(const uint4*)(smp + offA0 + (unsigned)s * 1024u);
            uint4 al = *(const uint4*)(smp + offA0 + (unsigned)s * 1024u + 512u);
            #pragma unroll
            for (int n = 0; n < 4; ++n) mma16816(D0[n], ah, bh[2*n], bh[2*n+1]);
            #pragma unroll
            for (int n = 0; n < 4; ++n) mma16816(D0[n], al, bh[2*n], bh[2*n+1]);
            #pragma unroll
            for (int n = 0; n < 4; ++n) mma16816(D0[n], ah, bl[2*n], bl[2*n+1]);

            if (two) {
                uint4 ah1 = *(const uint4*)(smp + offA1 + (unsigned)s * 1024u);
                uint4 al1 = *(const uint4*)(smp + offA1 + (unsigned)s * 1024u + 512u);
                #pragma unroll
                for (int n = 0; n < 4; ++n) mma16816(D1[n], ah1, bh[2*n], bh[2*n+1]);
                #pragma unroll
                for (int n = 0; n < 4; ++n) mma16816(D1[n], al1, bh[2*n], bh[2*n+1]);
                #pragma unroll
                for (int n = 0; n < 4; ++n) mma16816(D1[n], ah1, bl[2*n], bl[2*n+1]);
            }
        }
        // store gate pre-activations
        #pragma unroll
        for (int n = 0; n < 4; ++n) {
            *(float2*)(smp + offG0 + n * 32u)            = make_float2(D0[n][0], D0[n][1]);
            *(float2*)(smp + offG0 + n * 32u + 8u*160u)  = make_float2(D0[n][2], D0[n][3]);
            if (two) {
                *(float2*)(smp + offG1 + n * 32u)           = make_float2(D1[n][0], D1[n][1]);
                *(float2*)(smp + offG1 + n * 32u + 8u*160u) = make_float2(D1[n][2], D1[n][3]);
            }
        }
        __syncthreads();

        // ---- cells: cell2(t) + cell1(t+1) ----
        cells(t, t + 1 < Tt, true);
        __syncthreads();
    }

    // ---------------- final FC on h1(511) (f32 stash in G rows 200-249) ----------------
    if (tid < 32) {
        float acc = *(const float*)(smp + OFF_FC + 200);
        #pragma unroll
        for (int u = 0; u < Hh; ++u)
            acc += *(const float*)(smp + OFF_FC + u * 4)
                 * *(const float*)(smp + OFF_G + (200 + u) * 160u + tid * 4u);
        out[b0i + tid] = acc;
    }
}

extern "C" void kernel_launch(void* const* d_in, const int* in_sizes, int n_in,
                              void* d_out, int out_size)
{
    const float* x    = (const float*)d_in[0];
    const float* wih0 = (const float*)d_in[1];
    const float* whh0 = (const float*)d_in[2];
    const float* bih0 = (const float*)d_in[3];
    const float* bhh0 = (const float*)d_in[4];
    const float* wih1 = (const float*)d_in[5];
    const float* whh1 = (const float*)d_in[6];
    const float* bih1 = (const float*)d_in[7];
    const float* bhh1 = (const float*)d_in[8];
    const float* fcw  = (const float*)d_in[9];
    const float* fcb  = (const float*)d_in[10];
    float* out = (float*)d_out;

    const int B = in_sizes[0] / Tt;   // 4096
    const int grid = B / 32;          // 128

    cudaFuncSetAttribute(lstm2_hmma_kernel,
                         cudaFuncAttributeMaxDynamicSharedMemorySize, SMEM_BYTES);

    lstm2_hmma_kernel<<<grid, NT, SMEM_BYTES>>>(
        x, wih0, whh0, bih0, bhh0, wih1, whh1, bih1, bhh1, fcw, fcb, out);
}